// round 14
// baseline (speedup 1.0000x reference)
#include <cuda_runtime.h>
#include <cuda_bf16.h>
#include <cuda_fp16.h>
#include <cstdint>

// Problem constants (fixed shapes from reference)
#define B_  32
#define S_  512
#define H_  768
#define P_  76
#define K_  64
#define E_  768
#define M_  (B_ * P_)     // 2432
#define V_  50257
#define NK  (M_ * K_)     // 155648 candidate slots

// ---------------- device scratch (no allocs allowed) ----------------
__device__ __align__(16) float          g_lm[M_ * E_];    // pre-LN dense out
__device__ __align__(16) __half         g_lmn[M_ * E_];   // LayerNormed, fp16 (L2-resident)
__device__ __align__(16) __nv_bfloat16  g_ahi[M_ * H_];   // gathered A hi
__device__ __align__(16) __nv_bfloat16  g_alo[M_ * H_];   // gathered A lo
__device__ __align__(16) __nv_bfloat16  g_whi[H_ * E_];   // W hi (row-major = mma B)
__device__ __align__(16) __nv_bfloat16  g_wlo[H_ * E_];   // W lo
__device__ int g_cnt[V_];          // histogram
__device__ int g_cur[V_];          // scatter cursors
__device__ int g_off[V_ + 1];      // prefix offsets
__device__ int g_listv[NK];        // occurrence list: packed bp*64+k
__device__ int g_c64;              // cand idx int64?

// ---------------- helpers ----------------
__device__ __forceinline__ uint32_t smem_u32(const void* p) {
    uint32_t a;
    asm("{ .reg .u64 t; cvta.to.shared.u64 t, %1; cvt.u32.u64 %0, t; }"
        : "=r"(a) : "l"(p));
    return a;
}
__device__ __forceinline__ void cp16(uint32_t s, const void* g) {
    asm volatile("cp.async.cg.shared.global [%0], [%1], 16;" :: "r"(s), "l"(g));
}
__device__ __forceinline__ void ldm_x4(uint32_t* r, uint32_t addr) {
    asm volatile("ldmatrix.sync.aligned.m8n8.x4.shared.b16 {%0,%1,%2,%3}, [%4];"
                 : "=r"(r[0]), "=r"(r[1]), "=r"(r[2]), "=r"(r[3]) : "r"(addr));
}
__device__ __forceinline__ void ldm_x4_t(uint32_t* r, uint32_t addr) {
    asm volatile("ldmatrix.sync.aligned.m8n8.x4.trans.shared.b16 {%0,%1,%2,%3}, [%4];"
                 : "=r"(r[0]), "=r"(r[1]), "=r"(r[2]), "=r"(r[3]) : "r"(addr));
}
__device__ __forceinline__ void mma_bf16(float* d, const uint32_t* a,
                                         uint32_t b0, uint32_t b1) {
    asm volatile(
        "mma.sync.aligned.m16n8k16.row.col.f32.bf16.bf16.f32 "
        "{%0,%1,%2,%3}, {%4,%5,%6,%7}, {%8,%9}, {%0,%1,%2,%3};"
        : "+f"(d[0]), "+f"(d[1]), "+f"(d[2]), "+f"(d[3])
        : "r"(a[0]), "r"(a[1]), "r"(a[2]), "r"(a[3]), "r"(b0), "r"(b1));
}
__device__ __forceinline__ void split4(float4 v, uint2& hi, uint2& lo) {
    float vv[4] = { v.x, v.y, v.z, v.w };
    __nv_bfloat16 h[4], l[4];
#pragma unroll
    for (int c = 0; c < 4; c++) {
        h[c] = __float2bfloat16(vv[c]);
        l[c] = __float2bfloat16(vv[c] - __bfloat162float(h[c]));
    }
    __nv_bfloat162 h01(h[0], h[1]), h23(h[2], h[3]);
    __nv_bfloat162 l01(l[0], l[1]), l23(l[2], l[3]);
    hi.x = *(uint32_t*)&h01;  hi.y = *(uint32_t*)&h23;
    lo.x = *(uint32_t*)&l01;  lo.y = *(uint32_t*)&l23;
}

// ---------------------------------------------------------------------------
// Zero counters (before hist/scatter).
// ---------------------------------------------------------------------------
__global__ void __launch_bounds__(256)
zero_kernel()
{
    int i = blockIdx.x * 256 + threadIdx.x;
    if (i < V_) { g_cnt[i] = 0; g_cur[i] = 0; }
}

// ---------------------------------------------------------------------------
// Prep (496 blocks, float4-vectorized) -- proven R8 form (sets g_c64).
// ---------------------------------------------------------------------------
__global__ void __launch_bounds__(256)
prep_kernel(const float* __restrict__ seq, const int* __restrict__ mraw,
            const int* __restrict__ craw, const float* __restrict__ W)
{
    const int blk = blockIdx.x;
    const int tid = threadIdx.x;

    if (blk < 304) {
        __shared__ int nzm;
        if (tid == 0) nzm = 0;
        __syncthreads();
#pragma unroll
        for (int j = 0; j < 2; j++)
            if (mraw[2 * (tid + j * 256) + 1] != 0) atomicOr(&nzm, 1);  // 1024 w <= M_
        __syncthreads();
        const int m64 = (nzm == 0);
        if (tid < 192) {
#pragma unroll
            for (int j = 0; j < 8; j++) {
                const int m = blk * 8 + j;
                const int pos = m64 ? mraw[2 * m] : mraw[m];
                const int b = m / P_;
                const float4* src = (const float4*)(seq + (size_t)(b * S_ + pos) * H_);
                float4 v = src[tid];
                uint2 hi, lo;
                split4(v, hi, lo);
                *(uint2*)(g_ahi + (size_t)m * H_ + tid * 4) = hi;
                *(uint2*)(g_alo + (size_t)m * H_ + tid * 4) = lo;
            }
        }
    } else {
        const int blk2 = blk - 304;          // 0..191
        const int base = blk2 * 768;         // float4 units
        const float4* Wf4 = (const float4*)W;
#pragma unroll
        for (int i = 0; i < 3; i++) {
            int idx = base + i * 256 + tid;
            float4 v = Wf4[idx];
            uint2 hi, lo;
            split4(v, hi, lo);
            *(uint2*)(g_whi + (size_t)idx * 4) = hi;
            *(uint2*)(g_wlo + (size_t)idx * 4) = lo;
        }
        if (blk2 == 0) {
            __shared__ int nzc;
            if (tid == 0) nzc = 0;
            __syncthreads();
            if (craw[2 * tid + 1] != 0) atomicOr(&nzc, 1);   // 512 w <= NK
            __syncthreads();
            if (tid == 0) g_c64 = (nzc == 0);
        }
    }
}

// ---------------------------------------------------------------------------
// Inverted-index build: histogram -> scan -> scatter.
// ---------------------------------------------------------------------------
__global__ void __launch_bounds__(256)
hist_kernel(const int* __restrict__ craw)
{
    int i = blockIdx.x * 256 + threadIdx.x;          // grid 608 -> exactly NK
    int v = g_c64 ? craw[2 * i] : craw[i];
    atomicAdd(&g_cnt[v], 1);
}

__global__ void __launch_bounds__(1024)
scan_kernel()
{
    __shared__ int s[1024];
    const int t = threadIdx.x;
    const int lo = t * 50;
    const int hi = min(lo + 50, V_);
    int sum = 0;
    for (int i = lo; i < hi; i++) sum += g_cnt[i];
    s[t] = sum;
    __syncthreads();
    // Hillis-Steele inclusive scan
    for (int off = 1; off < 1024; off <<= 1) {
        int v = (t >= off) ? s[t - off] : 0;
        __syncthreads();
        s[t] += v;
        __syncthreads();
    }
    int run = s[t] - sum;                 // exclusive base for this thread
    for (int i = lo; i < hi; i++) {
        g_off[i] = run;
        run += g_cnt[i];
    }
    if (t == 1023) g_off[V_] = s[1023];
}

__global__ void __launch_bounds__(256)
scatter_kernel(const int* __restrict__ craw)
{
    int i = blockIdx.x * 256 + threadIdx.x;          // grid 608
    int v = g_c64 ? craw[2 * i] : craw[i];
    int pos = g_off[v] + atomicAdd(&g_cur[v], 1);
    g_listv[pos] = i;                                // i == bp*64 + k
}

// ---------------------------------------------------------------------------
// GEMM: EXACT R8 kernel. bf16 mma.sync m16n8k16, 3-term hi/lo split.
// 64x96 tile/CTA, grid 8 x 38 = 304 CTAs -> 2 resident CTAs/SM.
// ---------------------------------------------------------------------------
#define A_STR 40
#define B_STR 104

__global__ void __launch_bounds__(256)
gemm_mma_kernel(const float* __restrict__ bias)
{
    __shared__ __align__(16) __nv_bfloat16 sAhi[2][64][A_STR];
    __shared__ __align__(16) __nv_bfloat16 sAlo[2][64][A_STR];
    __shared__ __align__(16) __nv_bfloat16 sBhi[2][32][B_STR];
    __shared__ __align__(16) __nv_bfloat16 sBlo[2][32][B_STR];

    const int tid  = threadIdx.x;
    const int wid  = tid >> 5;
    const int lane = tid & 31;
    const int row0 = blockIdx.y * 64;
    const int col0 = blockIdx.x * 96;
    const int wm   = (wid >> 1) * 16;
    const int wn   = (wid & 1) * 48;

    const int ar = tid >> 2, ac = (tid & 3) * 8;
    const int br0 = tid / 12, bc0 = (tid % 12) * 8;
    const int br1 = (tid + 256) / 12, bc1 = ((tid + 256) % 12) * 8;

    float acc[6][4];
#pragma unroll
    for (int i = 0; i < 6; i++)
#pragma unroll
        for (int q = 0; q < 4; q++) acc[i][q] = 0.f;

    auto load_chunk = [&](int c, int buf) {
        const int k0 = c * 32;
        cp16(smem_u32(&sAhi[buf][ar][ac]), g_ahi + (size_t)(row0 + ar) * H_ + k0 + ac);
        cp16(smem_u32(&sAlo[buf][ar][ac]), g_alo + (size_t)(row0 + ar) * H_ + k0 + ac);
        cp16(smem_u32(&sBhi[buf][br0][bc0]), g_whi + (size_t)(k0 + br0) * E_ + col0 + bc0);
        cp16(smem_u32(&sBlo[buf][br0][bc0]), g_wlo + (size_t)(k0 + br0) * E_ + col0 + bc0);
        if (tid < 128) {
            cp16(smem_u32(&sBhi[buf][br1][bc1]), g_whi + (size_t)(k0 + br1) * E_ + col0 + bc1);
            cp16(smem_u32(&sBlo[buf][br1][bc1]), g_wlo + (size_t)(k0 + br1) * E_ + col0 + bc1);
        }
    };

    load_chunk(0, 0);
    asm volatile("cp.async.commit_group;" ::: "memory");

    const int l15 = lane & 15, lh = lane >> 4;

    for (int c = 0; c < 24; ++c) {
        const int buf = c & 1;
        if (c + 1 < 24) {
            load_chunk(c + 1, 1 - buf);
            asm volatile("cp.async.commit_group;" ::: "memory");
            asm volatile("cp.async.wait_group 1;" ::: "memory");
        } else {
            asm volatile("cp.async.wait_group 0;" ::: "memory");
        }
        __syncthreads();

#pragma unroll
        for (int ks = 0; ks < 2; ++ks) {
            uint32_t bh[3][4], bl[3][4];
#pragma unroll
            for (int g = 0; g < 3; ++g) {
                ldm_x4_t(bh[g], smem_u32(&sBhi[buf][ks * 16 + l15][wn + g * 16 + lh * 8]));
                ldm_x4_t(bl[g], smem_u32(&sBlo[buf][ks * 16 + l15][wn + g * 16 + lh * 8]));
            }
            uint32_t ah[4], al[4];
            ldm_x4(ah, smem_u32(&sAhi[buf][wm + l15][ks * 16 + lh * 8]));
            ldm_x4(al, smem_u32(&sAlo[buf][wm + l15][ks * 16 + lh * 8]));
#pragma unroll
            for (int g = 0; g < 3; ++g) {
#pragma unroll
                for (int s = 0; s < 2; ++s) {
                    float* d = acc[g * 2 + s];
                    mma_bf16(d, ah, bh[g][s * 2], bh[g][s * 2 + 1]);
                    mma_bf16(d, ah, bl[g][s * 2], bl[g][s * 2 + 1]);
                    mma_bf16(d, al, bh[g][s * 2], bh[g][s * 2 + 1]);
                }
            }
        }
        __syncthreads();
    }

    // Epilogue: + bias, fp32 store
    const int lr = lane >> 2, lc2 = (lane & 3) * 2;
#pragma unroll
    for (int nf = 0; nf < 6; ++nf) {
        const int col = col0 + wn + nf * 8 + lc2;
        const float2 bb = *(const float2*)(bias + col);
        const int r0 = row0 + wm + lr;
        float2 v0, v1;
        v0.x = acc[nf][0] + bb.x;  v0.y = acc[nf][1] + bb.y;
        v1.x = acc[nf][2] + bb.x;  v1.y = acc[nf][3] + bb.y;
        *(float2*)(g_lm + (size_t)r0 * E_ + col)       = v0;
        *(float2*)(g_lm + (size_t)(r0 + 8) * E_ + col) = v1;
    }
}

// ---------------------------------------------------------------------------
// LayerNorm: g_lm -> g_lmn (fp16).  One block per (b,p) row.
// ---------------------------------------------------------------------------
__global__ void __launch_bounds__(256)
ln_kernel(const float* __restrict__ gamma, const float* __restrict__ beta)
{
    __shared__ float red[16];
    __shared__ float mu_s, rinv_s;

    const int bp   = blockIdx.x;
    const int tid  = threadIdx.x;
    const int wid  = tid >> 5;
    const int lane = tid & 31;

    const float* row = g_lm + (size_t)bp * E_;
    float x0 = row[tid];
    float x1 = row[tid + 256];
    float x2 = row[tid + 512];

    float s  = x0 + x1 + x2;
    float sq = x0 * x0 + x1 * x1 + x2 * x2;
#pragma unroll
    for (int o = 16; o; o >>= 1) {
        s  += __shfl_xor_sync(0xffffffffu, s,  o);
        sq += __shfl_xor_sync(0xffffffffu, sq, o);
    }
    if (lane == 0) { red[wid] = s; red[wid + 8] = sq; }
    __syncthreads();
    if (tid == 0) {
        float S = 0.f, SQ = 0.f;
#pragma unroll
        for (int w = 0; w < 8; w++) { S += red[w]; SQ += red[w + 8]; }
        float mu  = S * (1.0f / E_);
        float var = SQ * (1.0f / E_) - mu * mu;
        mu_s   = mu;
        rinv_s = rsqrtf(var + 1e-12f);
    }
    __syncthreads();
    const float mu = mu_s, rinv = rinv_s;

    __half* dst = g_lmn + (size_t)bp * E_;
    dst[tid]       = __float2half_rn((x0 - mu) * rinv * gamma[tid]       + beta[tid]);
    dst[tid + 256] = __float2half_rn((x1 - mu) * rinv * gamma[tid + 256] + beta[tid + 256]);
    dst[tid + 512] = __float2half_rn((x2 - mu) * rinv * gamma[tid + 512] + beta[tid + 512]);
}

// ---------------------------------------------------------------------------
// Scatter-logits: one warp per vocab word.  Embedding row read ONCE from
// DRAM (streaming, 154MB compulsory); per-occurrence queries come from the
// L2-resident fp16 g_lmn (3.7MB).  Lane l owns elements [l*24, l*24+24).
// ---------------------------------------------------------------------------
#define SL_CTAS 1184
__global__ void __launch_bounds__(256)
slogits_kernel(const float* __restrict__ emb, float* __restrict__ out)
{
    const int wid  = threadIdx.x >> 5;
    const int lane = threadIdx.x & 31;
    const int gw   = blockIdx.x * 8 + wid;
    const int nw   = SL_CTAS * 8;

    for (int v = gw; v < V_; v += nw) {
        const int s = g_off[v];
        const int e = g_off[v + 1];
        if (s == e) continue;

        float4 er[6];
        const float4* ep = (const float4*)(emb + (size_t)v * E_ + lane * 24);
#pragma unroll
        for (int j = 0; j < 6; j++) er[j] = ep[j];

        for (int i = s; i < e; i++) {
            const int ent = g_listv[i];
            const int bp  = ent >> 6;
            const uint4* lp = (const uint4*)(g_lmn + (size_t)bp * E_ + lane * 24);
            float acc = 0.f;
#pragma unroll
            for (int j = 0; j < 3; j++) {
                uint4 q = lp[j];
                const float* f = (const float*)&er[j * 2];
                float2 a;
                a = __half22float2(*(__half2*)&q.x); acc += a.x * f[0] + a.y * f[1];
                a = __half22float2(*(__half2*)&q.y); acc += a.x * f[2] + a.y * f[3];
                a = __half22float2(*(__half2*)&q.z); acc += a.x * f[4] + a.y * f[5];
                a = __half22float2(*(__half2*)&q.w); acc += a.x * f[6] + a.y * f[7];
            }
#pragma unroll
            for (int o = 16; o; o >>= 1)
                acc += __shfl_xor_sync(0xffffffffu, acc, o);
            if (lane == 0) out[ent] = acc;
        }
    }
}

// ---------------------------------------------------------------------------
extern "C" void kernel_launch(void* const* d_in, const int* in_sizes, int n_in,
                              void* d_out, int out_size)
{
    const float* seq   = (const float*)d_in[0];
    const int*   mraw  = (const int*)d_in[1];
    const int*   craw  = (const int*)d_in[2];
    const float* emb   = (const float*)d_in[3];
    const float* W     = (const float*)d_in[4];
    const float* bias  = (const float*)d_in[5];
    const float* gamma = (const float*)d_in[6];
    const float* beta  = (const float*)d_in[7];
    float*       out   = (float*)d_out;

    zero_kernel<<<(V_ + 255) / 256, 256>>>();
    prep_kernel<<<496, 256>>>(seq, mraw, craw, W);          // sets g_c64
    hist_kernel<<<NK / 256, 256>>>(craw);
    scan_kernel<<<1, 1024>>>();
    scatter_kernel<<<NK / 256, 256>>>(craw);

    dim3 g1(E_ / 96, M_ / 64);   // 8 x 38 = 304 CTAs
    gemm_mma_kernel<<<g1, 256>>>(bias);
    ln_kernel<<<M_, 256>>>(gamma, beta);
    slogits_kernel<<<SL_CTAS, 256>>>(emb, out);
}

// round 15
// speedup vs baseline: 1.6106x; 1.6106x over previous
#include <cuda_runtime.h>
#include <cuda_bf16.h>
#include <cstdint>

// Problem constants (fixed shapes from reference)
#define B_  32
#define S_  512
#define H_  768
#define P_  76
#define K_  64
#define E_  768
#define M_  (B_ * P_)     // 2432

// ---------------- device scratch (no allocs allowed) ----------------
__device__ __align__(16) float          g_lm[M_ * E_];    // pre-LN dense out
__device__ __align__(16) __nv_bfloat16  g_ahi[M_ * H_];   // gathered A hi
__device__ __align__(16) __nv_bfloat16  g_alo[M_ * H_];   // gathered A lo
__device__ __align__(16) __nv_bfloat16  g_whi[H_ * E_];   // W hi (row-major = mma B)
__device__ __align__(16) __nv_bfloat16  g_wlo[H_ * E_];   // W lo
__device__ int g_c64;                                     // cand idx int64?

// ---------------- helpers ----------------
__device__ __forceinline__ uint32_t smem_u32(const void* p) {
    uint32_t a;
    asm("{ .reg .u64 t; cvta.to.shared.u64 t, %1; cvt.u32.u64 %0, t; }"
        : "=r"(a) : "l"(p));
    return a;
}
__device__ __forceinline__ void cp16(uint32_t s, const void* g) {
    asm volatile("cp.async.cg.shared.global [%0], [%1], 16;" :: "r"(s), "l"(g));
}
__device__ __forceinline__ void ldm_x4(uint32_t* r, uint32_t addr) {
    asm volatile("ldmatrix.sync.aligned.m8n8.x4.shared.b16 {%0,%1,%2,%3}, [%4];"
                 : "=r"(r[0]), "=r"(r[1]), "=r"(r[2]), "=r"(r[3]) : "r"(addr));
}
__device__ __forceinline__ void ldm_x4_t(uint32_t* r, uint32_t addr) {
    asm volatile("ldmatrix.sync.aligned.m8n8.x4.trans.shared.b16 {%0,%1,%2,%3}, [%4];"
                 : "=r"(r[0]), "=r"(r[1]), "=r"(r[2]), "=r"(r[3]) : "r"(addr));
}
__device__ __forceinline__ void mma_bf16(float* d, const uint32_t* a,
                                         uint32_t b0, uint32_t b1) {
    asm volatile(
        "mma.sync.aligned.m16n8k16.row.col.f32.bf16.bf16.f32 "
        "{%0,%1,%2,%3}, {%4,%5,%6,%7}, {%8,%9}, {%0,%1,%2,%3};"
        : "+f"(d[0]), "+f"(d[1]), "+f"(d[2]), "+f"(d[3])
        : "r"(a[0]), "r"(a[1]), "r"(a[2]), "r"(a[3]), "r"(b0), "r"(b1));
}
__device__ __forceinline__ void split4(float4 v, uint2& hi, uint2& lo) {
    float vv[4] = { v.x, v.y, v.z, v.w };
    __nv_bfloat16 h[4], l[4];
#pragma unroll
    for (int c = 0; c < 4; c++) {
        h[c] = __float2bfloat16(vv[c]);
        l[c] = __float2bfloat16(vv[c] - __bfloat162float(h[c]));
    }
    __nv_bfloat162 h01(h[0], h[1]), h23(h[2], h[3]);
    __nv_bfloat162 l01(l[0], l[1]), l23(l[2], l[3]);
    hi.x = *(uint32_t*)&h01;  hi.y = *(uint32_t*)&h23;
    lo.x = *(uint32_t*)&l01;  lo.y = *(uint32_t*)&l23;
}

// ---------------------------------------------------------------------------
// Prep (496 blocks, float4-vectorized) -- proven R8 form.
// ---------------------------------------------------------------------------
__global__ void __launch_bounds__(256)
prep_kernel(const float* __restrict__ seq, const int* __restrict__ mraw,
            const int* __restrict__ craw, const float* __restrict__ W)
{
    const int blk = blockIdx.x;
    const int tid = threadIdx.x;

    if (blk < 304) {
        __shared__ int nzm;
        if (tid == 0) nzm = 0;
        __syncthreads();
#pragma unroll
        for (int j = 0; j < 2; j++)
            if (mraw[2 * (tid + j * 256) + 1] != 0) atomicOr(&nzm, 1);  // 1024 w <= M_
        __syncthreads();
        const int m64 = (nzm == 0);
        if (tid < 192) {
#pragma unroll
            for (int j = 0; j < 8; j++) {
                const int m = blk * 8 + j;
                const int pos = m64 ? mraw[2 * m] : mraw[m];
                const int b = m / P_;
                const float4* src = (const float4*)(seq + (size_t)(b * S_ + pos) * H_);
                float4 v = src[tid];
                uint2 hi, lo;
                split4(v, hi, lo);
                *(uint2*)(g_ahi + (size_t)m * H_ + tid * 4) = hi;
                *(uint2*)(g_alo + (size_t)m * H_ + tid * 4) = lo;
            }
        }
    } else {
        const int blk2 = blk - 304;          // 0..191
        const int base = blk2 * 768;         // float4 units
        const float4* Wf4 = (const float4*)W;
#pragma unroll
        for (int i = 0; i < 3; i++) {
            int idx = base + i * 256 + tid;
            float4 v = Wf4[idx];
            uint2 hi, lo;
            split4(v, hi, lo);
            *(uint2*)(g_whi + (size_t)idx * 4) = hi;
            *(uint2*)(g_wlo + (size_t)idx * 4) = lo;
        }
        if (blk2 == 0) {
            __shared__ int nzc;
            if (tid == 0) nzc = 0;
            __syncthreads();
            if (craw[2 * tid + 1] != 0) atomicOr(&nzc, 1);   // 512 w <= M_*K_
            __syncthreads();
            if (tid == 0) g_c64 = (nzc == 0);
        }
    }
}

// ---------------------------------------------------------------------------
// GEMM: bf16 mma.sync m16n8k16, 3-term hi/lo split, 3-STAGE cp.async pipeline
// (prefetch distance 2 hides global latency better than the 2-stage version).
// 64x96 tile/CTA, grid 8 x 38 = 304 CTAs -> 2 resident CTAs/SM (138KB smem).
// Dynamic smem: 3 bufs x (A hi/lo 64x40 + B hi/lo 32x104) bf16 = 69KB.
// ---------------------------------------------------------------------------
#define A_STR 40
#define B_STR 104
#define A_BUF (64 * A_STR)                 // bf16 elems per A buffer
#define B_BUF (32 * B_STR)                 // bf16 elems per B buffer
#define GEMM_SMEM ((2 * 3 * A_BUF + 2 * 3 * B_BUF) * 2)   // bytes = 69504

__global__ void __launch_bounds__(256)
gemm_mma_kernel(const float* __restrict__ bias)
{
    extern __shared__ __align__(16) __nv_bfloat16 dsm[];
    __nv_bfloat16* sAhi = dsm;                       // [3][64][A_STR]
    __nv_bfloat16* sAlo = sAhi + 3 * A_BUF;
    __nv_bfloat16* sBhi = sAlo + 3 * A_BUF;          // [3][32][B_STR]
    __nv_bfloat16* sBlo = sBhi + 3 * B_BUF;

    const int tid  = threadIdx.x;
    const int wid  = tid >> 5;
    const int lane = tid & 31;
    const int row0 = blockIdx.y * 64;
    const int col0 = blockIdx.x * 96;
    const int wm   = (wid >> 1) * 16;
    const int wn   = (wid & 1) * 48;

    const int ar = tid >> 2, ac = (tid & 3) * 8;
    const int br0 = tid / 12, bc0 = (tid % 12) * 8;
    const int br1 = (tid + 256) / 12, bc1 = ((tid + 256) % 12) * 8;

    float acc[6][4];
#pragma unroll
    for (int i = 0; i < 6; i++)
#pragma unroll
        for (int q = 0; q < 4; q++) acc[i][q] = 0.f;

    auto load_chunk = [&](int c, int buf) {
        const int k0 = c * 32;
        cp16(smem_u32(sAhi + buf * A_BUF + ar * A_STR + ac),
             g_ahi + (size_t)(row0 + ar) * H_ + k0 + ac);
        cp16(smem_u32(sAlo + buf * A_BUF + ar * A_STR + ac),
             g_alo + (size_t)(row0 + ar) * H_ + k0 + ac);
        cp16(smem_u32(sBhi + buf * B_BUF + br0 * B_STR + bc0),
             g_whi + (size_t)(k0 + br0) * E_ + col0 + bc0);
        cp16(smem_u32(sBlo + buf * B_BUF + br0 * B_STR + bc0),
             g_wlo + (size_t)(k0 + br0) * E_ + col0 + bc0);
        if (tid < 128) {
            cp16(smem_u32(sBhi + buf * B_BUF + br1 * B_STR + bc1),
                 g_whi + (size_t)(k0 + br1) * E_ + col0 + bc1);
            cp16(smem_u32(sBlo + buf * B_BUF + br1 * B_STR + bc1),
                 g_wlo + (size_t)(k0 + br1) * E_ + col0 + bc1);
        }
    };

    load_chunk(0, 0);
    asm volatile("cp.async.commit_group;" ::: "memory");
    load_chunk(1, 1);
    asm volatile("cp.async.commit_group;" ::: "memory");

    const int l15 = lane & 15, lh = lane >> 4;

    for (int c = 0; c < 24; ++c) {
        const int buf = c % 3;
        if (c < 22) {
            load_chunk(c + 2, (c + 2) % 3);
            asm volatile("cp.async.commit_group;" ::: "memory");
            asm volatile("cp.async.wait_group 2;" ::: "memory");
        } else if (c == 22) {
            asm volatile("cp.async.wait_group 1;" ::: "memory");
        } else {
            asm volatile("cp.async.wait_group 0;" ::: "memory");
        }
        __syncthreads();

        const __nv_bfloat16* Ah = sAhi + buf * A_BUF;
        const __nv_bfloat16* Al = sAlo + buf * A_BUF;
        const __nv_bfloat16* Bh = sBhi + buf * B_BUF;
        const __nv_bfloat16* Bl = sBlo + buf * B_BUF;

#pragma unroll
        for (int ks = 0; ks < 2; ++ks) {
            uint32_t bh[3][4], bl[3][4];
#pragma unroll
            for (int g = 0; g < 3; ++g) {
                ldm_x4_t(bh[g], smem_u32(Bh + (ks * 16 + l15) * B_STR + wn + g * 16 + lh * 8));
                ldm_x4_t(bl[g], smem_u32(Bl + (ks * 16 + l15) * B_STR + wn + g * 16 + lh * 8));
            }
            uint32_t ah[4], al[4];
            ldm_x4(ah, smem_u32(Ah + (wm + l15) * A_STR + ks * 16 + lh * 8));
            ldm_x4(al, smem_u32(Al + (wm + l15) * A_STR + ks * 16 + lh * 8));
#pragma unroll
            for (int g = 0; g < 3; ++g) {
#pragma unroll
                for (int s = 0; s < 2; ++s) {
                    float* d = acc[g * 2 + s];
                    mma_bf16(d, ah, bh[g][s * 2], bh[g][s * 2 + 1]);
                    mma_bf16(d, ah, bl[g][s * 2], bl[g][s * 2 + 1]);
                    mma_bf16(d, al, bh[g][s * 2], bh[g][s * 2 + 1]);
                }
            }
        }
        __syncthreads();
    }

    // Epilogue: + bias, fp32 store
    const int lr = lane >> 2, lc2 = (lane & 3) * 2;
#pragma unroll
    for (int nf = 0; nf < 6; ++nf) {
        const int col = col0 + wn + nf * 8 + lc2;
        const float2 bb = *(const float2*)(bias + col);
        const int r0 = row0 + wm + lr;
        float2 v0, v1;
        v0.x = acc[nf][0] + bb.x;  v0.y = acc[nf][1] + bb.y;
        v1.x = acc[nf][2] + bb.x;  v1.y = acc[nf][3] + bb.y;
        *(float2*)(g_lm + (size_t)r0 * E_ + col)       = v0;
        *(float2*)(g_lm + (size_t)(r0 + 8) * E_ + col) = v1;
    }
}

// ---------------------------------------------------------------------------
// Logits: per-(b,p) LayerNorm (fused) + 64 candidate dots, fp32 table
// (proven R8 version, 53.4us; within ~25% of its 42us L2 roofline).
// ---------------------------------------------------------------------------
__global__ void __launch_bounds__(256)
logits_kernel(const int*   __restrict__ craw,
              const float* __restrict__ emb,
              const float* __restrict__ gamma,
              const float* __restrict__ beta,
              float* __restrict__ out)
{
    __shared__ __align__(16) float lm_s[E_];
    __shared__ float red[16];
    __shared__ float mu_s, rinv_s;

    const int bp   = blockIdx.x;
    const int tid  = threadIdx.x;
    const int wid  = tid >> 5;
    const int lane = tid & 31;
    const int c64  = g_c64;

    const float* row = g_lm + (size_t)bp * E_;
    float x0 = row[tid];
    float x1 = row[tid + 256];
    float x2 = row[tid + 512];

    float s  = x0 + x1 + x2;
    float sq = x0 * x0 + x1 * x1 + x2 * x2;
#pragma unroll
    for (int o = 16; o; o >>= 1) {
        s  += __shfl_xor_sync(0xffffffffu, s,  o);
        sq += __shfl_xor_sync(0xffffffffu, sq, o);
    }
    if (lane == 0) { red[wid] = s; red[wid + 8] = sq; }
    __syncthreads();
    if (tid == 0) {
        float S = 0.f, SQ = 0.f;
#pragma unroll
        for (int w = 0; w < 8; w++) { S += red[w]; SQ += red[w + 8]; }
        float mu  = S * (1.0f / E_);
        float var = SQ * (1.0f / E_) - mu * mu;
        mu_s   = mu;
        rinv_s = rsqrtf(var + 1e-12f);
    }
    __syncthreads();
    const float mu = mu_s, rinv = rinv_s;

    lm_s[tid]       = (x0 - mu) * rinv * gamma[tid]       + beta[tid];
    lm_s[tid + 256] = (x1 - mu) * rinv * gamma[tid + 256] + beta[tid + 256];
    lm_s[tid + 512] = (x2 - mu) * rinv * gamma[tid + 512] + beta[tid + 512];
    __syncthreads();

    const float4* lp = (const float4*)lm_s;

#pragma unroll
    for (int kk = 0; kk < 4; kk++) {
        int k  = wid * 8 + kk * 2;
        int i0 = bp * K_ + k;
        int c0 = c64 ? craw[2 * i0]     : craw[i0];
        int c1 = c64 ? craw[2 * i0 + 2] : craw[i0 + 1];
        const float4* e0 = (const float4*)(emb + (size_t)c0 * E_);
        const float4* e1 = (const float4*)(emb + (size_t)c1 * E_);
        float a0 = 0.f, a1 = 0.f;
#pragma unroll
        for (int j = 0; j < 6; j++) {
            float4 l  = lp[j * 32 + lane];
            float4 v0 = e0[j * 32 + lane];
            float4 v1 = e1[j * 32 + lane];
            a0 += v0.x * l.x + v0.y * l.y + v0.z * l.z + v0.w * l.w;
            a1 += v1.x * l.x + v1.y * l.y + v1.z * l.z + v1.w * l.w;
        }
#pragma unroll
        for (int o = 16; o; o >>= 1) {
            a0 += __shfl_xor_sync(0xffffffffu, a0, o);
            a1 += __shfl_xor_sync(0xffffffffu, a1, o);
        }
        if (lane == 0) {
            out[i0]     = a0;
            out[i0 + 1] = a1;
        }
    }
}

// ---------------------------------------------------------------------------
extern "C" void kernel_launch(void* const* d_in, const int* in_sizes, int n_in,
                              void* d_out, int out_size)
{
    const float* seq   = (const float*)d_in[0];
    const int*   mraw  = (const int*)d_in[1];
    const int*   craw  = (const int*)d_in[2];
    const float* emb   = (const float*)d_in[3];
    const float* W     = (const float*)d_in[4];
    const float* bias  = (const float*)d_in[5];
    const float* gamma = (const float*)d_in[6];
    const float* beta  = (const float*)d_in[7];
    float*       out   = (float*)d_out;

    static bool attr_set = false;
    if (!attr_set) {
        cudaFuncSetAttribute(gemm_mma_kernel,
                             cudaFuncAttributeMaxDynamicSharedMemorySize,
                             GEMM_SMEM);
        attr_set = true;
    }

    prep_kernel<<<496, 256>>>(seq, mraw, craw, W);
    dim3 g1(E_ / 96, M_ / 64);   // 8 x 38 = 304 CTAs
    gemm_mma_kernel<<<g1, 256, GEMM_SMEM>>>(bias);
    logits_kernel<<<M_, 256>>>(craw, emb, gamma, beta, out);
}

// round 16
// speedup vs baseline: 1.6483x; 1.0234x over previous
#include <cuda_runtime.h>
#include <cuda_bf16.h>
#include <cstdint>

// Problem constants (fixed shapes from reference)
#define B_  32
#define S_  512
#define H_  768
#define P_  76
#define K_  64
#define E_  768
#define M_  (B_ * P_)     // 2432

// ---------------- device scratch (no allocs allowed) ----------------
__device__ __align__(16) float          g_lm[M_ * E_];    // pre-LN dense out
__device__ __align__(16) __nv_bfloat16  g_ahi[M_ * H_];   // gathered A hi
__device__ __align__(16) __nv_bfloat16  g_alo[M_ * H_];   // gathered A lo
__device__ __align__(16) __nv_bfloat16  g_whi[H_ * E_];   // W hi (row-major = mma B)
__device__ __align__(16) __nv_bfloat16  g_wlo[H_ * E_];   // W lo
__device__ int g_c64;                                     // cand idx int64?

// ---------------- helpers ----------------
__device__ __forceinline__ uint32_t smem_u32(const void* p) {
    uint32_t a;
    asm("{ .reg .u64 t; cvta.to.shared.u64 t, %1; cvt.u32.u64 %0, t; }"
        : "=r"(a) : "l"(p));
    return a;
}
__device__ __forceinline__ void cp16(uint32_t s, const void* g) {
    asm volatile("cp.async.cg.shared.global [%0], [%1], 16;" :: "r"(s), "l"(g));
}
__device__ __forceinline__ void ldm_x4(uint32_t* r, uint32_t addr) {
    asm volatile("ldmatrix.sync.aligned.m8n8.x4.shared.b16 {%0,%1,%2,%3}, [%4];"
                 : "=r"(r[0]), "=r"(r[1]), "=r"(r[2]), "=r"(r[3]) : "r"(addr));
}
__device__ __forceinline__ void ldm_x4_t(uint32_t* r, uint32_t addr) {
    asm volatile("ldmatrix.sync.aligned.m8n8.x4.trans.shared.b16 {%0,%1,%2,%3}, [%4];"
                 : "=r"(r[0]), "=r"(r[1]), "=r"(r[2]), "=r"(r[3]) : "r"(addr));
}
__device__ __forceinline__ void mma_bf16(float* d, const uint32_t* a,
                                         uint32_t b0, uint32_t b1) {
    asm volatile(
        "mma.sync.aligned.m16n8k16.row.col.f32.bf16.bf16.f32 "
        "{%0,%1,%2,%3}, {%4,%5,%6,%7}, {%8,%9}, {%0,%1,%2,%3};"
        : "+f"(d[0]), "+f"(d[1]), "+f"(d[2]), "+f"(d[3])
        : "r"(a[0]), "r"(a[1]), "r"(a[2]), "r"(a[3]), "r"(b0), "r"(b1));
}
__device__ __forceinline__ void split4(float4 v, uint2& hi, uint2& lo) {
    float vv[4] = { v.x, v.y, v.z, v.w };
    __nv_bfloat16 h[4], l[4];
#pragma unroll
    for (int c = 0; c < 4; c++) {
        h[c] = __float2bfloat16(vv[c]);
        l[c] = __float2bfloat16(vv[c] - __bfloat162float(h[c]));
    }
    __nv_bfloat162 h01(h[0], h[1]), h23(h[2], h[3]);
    __nv_bfloat162 l01(l[0], l[1]), l23(l[2], l[3]);
    hi.x = *(uint32_t*)&h01;  hi.y = *(uint32_t*)&h23;
    lo.x = *(uint32_t*)&l01;  lo.y = *(uint32_t*)&l23;
}

// ---------------------------------------------------------------------------
// Prep (496 blocks, float4-vectorized) -- proven R8 form.
// ---------------------------------------------------------------------------
__global__ void __launch_bounds__(256)
prep_kernel(const float* __restrict__ seq, const int* __restrict__ mraw,
            const int* __restrict__ craw, const float* __restrict__ W)
{
    const int blk = blockIdx.x;
    const int tid = threadIdx.x;

    if (blk < 304) {
        __shared__ int nzm;
        if (tid == 0) nzm = 0;
        __syncthreads();
#pragma unroll
        for (int j = 0; j < 2; j++)
            if (mraw[2 * (tid + j * 256) + 1] != 0) atomicOr(&nzm, 1);  // 1024 w <= M_
        __syncthreads();
        const int m64 = (nzm == 0);
        if (tid < 192) {
#pragma unroll
            for (int j = 0; j < 8; j++) {
                const int m = blk * 8 + j;
                const int pos = m64 ? mraw[2 * m] : mraw[m];
                const int b = m / P_;
                const float4* src = (const float4*)(seq + (size_t)(b * S_ + pos) * H_);
                float4 v = src[tid];
                uint2 hi, lo;
                split4(v, hi, lo);
                *(uint2*)(g_ahi + (size_t)m * H_ + tid * 4) = hi;
                *(uint2*)(g_alo + (size_t)m * H_ + tid * 4) = lo;
            }
        }
    } else {
        const int blk2 = blk - 304;          // 0..191
        const int base = blk2 * 768;         // float4 units
        const float4* Wf4 = (const float4*)W;
#pragma unroll
        for (int i = 0; i < 3; i++) {
            int idx = base + i * 256 + tid;
            float4 v = Wf4[idx];
            uint2 hi, lo;
            split4(v, hi, lo);
            *(uint2*)(g_whi + (size_t)idx * 4) = hi;
            *(uint2*)(g_wlo + (size_t)idx * 4) = lo;
        }
        if (blk2 == 0) {
            __shared__ int nzc;
            if (tid == 0) nzc = 0;
            __syncthreads();
            if (craw[2 * tid + 1] != 0) atomicOr(&nzc, 1);   // 512 w <= M_*K_
            __syncthreads();
            if (tid == 0) g_c64 = (nzc == 0);
        }
    }
}

// ---------------------------------------------------------------------------
// GEMM: EXACT R8 kernel (bf16 mma.sync, 3-term hi/lo split, 2-stage pipeline,
// static 47KB smem, 64x96 tile, 8x38=304 CTAs, 2/SM) PLUS register-free
// prefetch.global.L2 of the first ~119.5MB of the embedding table, hidden
// under the tensor-bound window to pre-warm L2 for the logits kernel.
// ---------------------------------------------------------------------------
#define A_STR 40
#define B_STR 104

__global__ void __launch_bounds__(256)
gemm_mma_kernel(const float* __restrict__ bias, const char* __restrict__ embc)
{
    __shared__ __align__(16) __nv_bfloat16 sAhi[2][64][A_STR];
    __shared__ __align__(16) __nv_bfloat16 sAlo[2][64][A_STR];
    __shared__ __align__(16) __nv_bfloat16 sBhi[2][32][B_STR];
    __shared__ __align__(16) __nv_bfloat16 sBlo[2][32][B_STR];

    const int tid  = threadIdx.x;
    const int wid  = tid >> 5;
    const int lane = tid & 31;
    const int row0 = blockIdx.y * 64;
    const int col0 = blockIdx.x * 96;
    const int bid  = blockIdx.y * 8 + blockIdx.x;   // 0..303
    const int wm   = (wid >> 1) * 16;
    const int wn   = (wid & 1) * 48;

    const int ar = tid >> 2, ac = (tid & 3) * 8;
    const int br0 = tid / 12, bc0 = (tid % 12) * 8;
    const int br1 = (tid + 256) / 12, bc1 = ((tid + 256) % 12) * 8;

    float acc[6][4];
#pragma unroll
    for (int i = 0; i < 6; i++)
#pragma unroll
        for (int q = 0; q < 4; q++) acc[i][q] = 0.f;

    auto load_chunk = [&](int c, int buf) {
        const int k0 = c * 32;
        cp16(smem_u32(&sAhi[buf][ar][ac]), g_ahi + (size_t)(row0 + ar) * H_ + k0 + ac);
        cp16(smem_u32(&sAlo[buf][ar][ac]), g_alo + (size_t)(row0 + ar) * H_ + k0 + ac);
        cp16(smem_u32(&sBhi[buf][br0][bc0]), g_whi + (size_t)(k0 + br0) * E_ + col0 + bc0);
        cp16(smem_u32(&sBlo[buf][br0][bc0]), g_wlo + (size_t)(k0 + br0) * E_ + col0 + bc0);
        if (tid < 128) {
            cp16(smem_u32(&sBhi[buf][br1][bc1]), g_whi + (size_t)(k0 + br1) * E_ + col0 + bc1);
            cp16(smem_u32(&sBlo[buf][br1][bc1]), g_wlo + (size_t)(k0 + br1) * E_ + col0 + bc1);
        }
    };

    load_chunk(0, 0);
    asm volatile("cp.async.commit_group;" ::: "memory");

    const int l15 = lane & 15, lh = lane >> 4;

    for (int c = 0; c < 24; ++c) {
        const int buf = c & 1;
        if (c + 1 < 24) {
            load_chunk(c + 1, 1 - buf);
            asm volatile("cp.async.commit_group;" ::: "memory");
            asm volatile("cp.async.wait_group 1;" ::: "memory");
        } else {
            asm volatile("cp.async.wait_group 0;" ::: "memory");
        }

        // Register-free L2 prefetch of the embedding table: 304 CTAs x 24
        // chunks x 128 lines x 128B = 119.5MB (< L2 capacity).  No scoreboard,
        // no destination register -- pure issue-slot cost under MMA shadow.
        if (tid < 128) {
            const long line = ((long)bid * 24 + c) * 128 + tid;
            asm volatile("prefetch.global.L2 [%0];" :: "l"(embc + line * 128));
        }
        __syncthreads();

#pragma unroll
        for (int ks = 0; ks < 2; ++ks) {
            uint32_t bh[3][4], bl[3][4];
#pragma unroll
            for (int g = 0; g < 3; ++g) {
                ldm_x4_t(bh[g], smem_u32(&sBhi[buf][ks * 16 + l15][wn + g * 16 + lh * 8]));
                ldm_x4_t(bl[g], smem_u32(&sBlo[buf][ks * 16 + l15][wn + g * 16 + lh * 8]));
            }
            uint32_t ah[4], al[4];
            ldm_x4(ah, smem_u32(&sAhi[buf][wm + l15][ks * 16 + lh * 8]));
            ldm_x4(al, smem_u32(&sAlo[buf][wm + l15][ks * 16 + lh * 8]));
#pragma unroll
            for (int g = 0; g < 3; ++g) {
#pragma unroll
                for (int s = 0; s < 2; ++s) {
                    float* d = acc[g * 2 + s];
                    mma_bf16(d, ah, bh[g][s * 2], bh[g][s * 2 + 1]);
                    mma_bf16(d, ah, bl[g][s * 2], bl[g][s * 2 + 1]);
                    mma_bf16(d, al, bh[g][s * 2], bh[g][s * 2 + 1]);
                }
            }
        }
        __syncthreads();
    }

    // Epilogue: + bias, fp32 store
    const int lr = lane >> 2, lc2 = (lane & 3) * 2;
#pragma unroll
    for (int nf = 0; nf < 6; ++nf) {
        const int col = col0 + wn + nf * 8 + lc2;
        const float2 bb = *(const float2*)(bias + col);
        const int r0 = row0 + wm + lr;
        float2 v0, v1;
        v0.x = acc[nf][0] + bb.x;  v0.y = acc[nf][1] + bb.y;
        v1.x = acc[nf][2] + bb.x;  v1.y = acc[nf][3] + bb.y;
        *(float2*)(g_lm + (size_t)r0 * E_ + col)       = v0;
        *(float2*)(g_lm + (size_t)(r0 + 8) * E_ + col) = v1;
    }
}

// ---------------------------------------------------------------------------
// Logits: per-(b,p) LayerNorm (fused) + 64 candidate dots, fp32 table
// (proven R8 version; table now largely L2-warm from the GEMM's prefetch).
// ---------------------------------------------------------------------------
__global__ void __launch_bounds__(256)
logits_kernel(const int*   __restrict__ craw,
              const float* __restrict__ emb,
              const float* __restrict__ gamma,
              const float* __restrict__ beta,
              float* __restrict__ out)
{
    __shared__ __align__(16) float lm_s[E_];
    __shared__ float red[16];
    __shared__ float mu_s, rinv_s;

    const int bp   = blockIdx.x;
    const int tid  = threadIdx.x;
    const int wid  = tid >> 5;
    const int lane = tid & 31;
    const int c64  = g_c64;

    const float* row = g_lm + (size_t)bp * E_;
    float x0 = row[tid];
    float x1 = row[tid + 256];
    float x2 = row[tid + 512];

    float s  = x0 + x1 + x2;
    float sq = x0 * x0 + x1 * x1 + x2 * x2;
#pragma unroll
    for (int o = 16; o; o >>= 1) {
        s  += __shfl_xor_sync(0xffffffffu, s,  o);
        sq += __shfl_xor_sync(0xffffffffu, sq, o);
    }
    if (lane == 0) { red[wid] = s; red[wid + 8] = sq; }
    __syncthreads();
    if (tid == 0) {
        float S = 0.f, SQ = 0.f;
#pragma unroll
        for (int w = 0; w < 8; w++) { S += red[w]; SQ += red[w + 8]; }
        float mu  = S * (1.0f / E_);
        float var = SQ * (1.0f / E_) - mu * mu;
        mu_s   = mu;
        rinv_s = rsqrtf(var + 1e-12f);
    }
    __syncthreads();
    const float mu = mu_s, rinv = rinv_s;

    lm_s[tid]       = (x0 - mu) * rinv * gamma[tid]       + beta[tid];
    lm_s[tid + 256] = (x1 - mu) * rinv * gamma[tid + 256] + beta[tid + 256];
    lm_s[tid + 512] = (x2 - mu) * rinv * gamma[tid + 512] + beta[tid + 512];
    __syncthreads();

    const float4* lp = (const float4*)lm_s;

#pragma unroll
    for (int kk = 0; kk < 4; kk++) {
        int k  = wid * 8 + kk * 2;
        int i0 = bp * K_ + k;
        int c0 = c64 ? craw[2 * i0]     : craw[i0];
        int c1 = c64 ? craw[2 * i0 + 2] : craw[i0 + 1];
        const float4* e0 = (const float4*)(emb + (size_t)c0 * E_);
        const float4* e1 = (const float4*)(emb + (size_t)c1 * E_);
        float a0 = 0.f, a1 = 0.f;
#pragma unroll
        for (int j = 0; j < 6; j++) {
            float4 l  = lp[j * 32 + lane];
            float4 v0 = e0[j * 32 + lane];
            float4 v1 = e1[j * 32 + lane];
            a0 += v0.x * l.x + v0.y * l.y + v0.z * l.z + v0.w * l.w;
            a1 += v1.x * l.x + v1.y * l.y + v1.z * l.z + v1.w * l.w;
        }
#pragma unroll
        for (int o = 16; o; o >>= 1) {
            a0 += __shfl_xor_sync(0xffffffffu, a0, o);
            a1 += __shfl_xor_sync(0xffffffffu, a1, o);
        }
        if (lane == 0) {
            out[i0]     = a0;
            out[i0 + 1] = a1;
        }
    }
}

// ---------------------------------------------------------------------------
extern "C" void kernel_launch(void* const* d_in, const int* in_sizes, int n_in,
                              void* d_out, int out_size)
{
    const float* seq   = (const float*)d_in[0];
    const int*   mraw  = (const int*)d_in[1];
    const int*   craw  = (const int*)d_in[2];
    const float* emb   = (const float*)d_in[3];
    const float* W     = (const float*)d_in[4];
    const float* bias  = (const float*)d_in[5];
    const float* gamma = (const float*)d_in[6];
    const float* beta  = (const float*)d_in[7];
    float*       out   = (float*)d_out;

    prep_kernel<<<496, 256>>>(seq, mraw, craw, W);
    dim3 g1(E_ / 96, M_ / 64);   // 8 x 38 = 304 CTAs
    gemm_mma_kernel<<<g1, 256>>>(bias, (const char*)emb);
    logits_kernel<<<M_, 256>>>(craw, emb, gamma, beta, out);
}